// round 1
// baseline (speedup 1.0000x reference)
#include <cuda_runtime.h>
#include <cuda_bf16.h>
#include <cstdint>

#define NN 16384
#define DH 128      // hidden dim
#define TT 256      // input/output dim
#define BQ 64       // query rows per block
#define BK 64       // key rows per tile
#define QK_PAD 68   // padded row stride for k-major Q/K smem tiles (16B aligned, conflict-free)
#define P_PAD 68

// scratch (device globals: allocation-guard safe)
__device__ float g_Q[NN * DH];
__device__ float g_K[NN * DH];

// ---------------------------------------------------------------------------
// Kernel 1: Q = H*Wq + bq  /  K = H*Wk + bk   (blockIdx.y selects)
// 128x128 output tile per block, K-chunks of 32.
// ---------------------------------------------------------------------------
__global__ __launch_bounds__(256)
void qk_kernel(const float* __restrict__ H,
               const float* __restrict__ Wq, const float* __restrict__ bq,
               const float* __restrict__ Wk, const float* __restrict__ bk) {
    __shared__ float HsT[32 * 129];   // [k][row], pad 129 avoids write conflicts
    __shared__ float Ws[32 * 128];    // [k][col]

    const float* W = blockIdx.y ? Wk : Wq;
    const float* b = blockIdx.y ? bk : bq;
    float* outp    = blockIdx.y ? g_K : g_Q;

    const int tid = threadIdx.x;
    const int ty = tid >> 4;          // 0..15 -> 8 rows each
    const int tx = tid & 15;          // 0..15 -> 8 cols each
    const int row0 = blockIdx.x * 128;

    float acc[8][8];
    #pragma unroll
    for (int i = 0; i < 8; i++)
        #pragma unroll
        for (int j = 0; j < 8; j++) acc[i][j] = 0.f;

    for (int kc = 0; kc < TT; kc += 32) {
        __syncthreads();
        // load H tile transposed: HsT[k][r] = H[row0+r][kc+k]
        #pragma unroll
        for (int idx = tid; idx < 128 * 32; idx += 256) {
            int r = idx >> 5, k = idx & 31;
            HsT[k * 129 + r] = H[(size_t)(row0 + r) * TT + kc + k];
        }
        // load W tile: Ws[k][c] = W[kc+k][c]
        #pragma unroll
        for (int idx = tid; idx < 32 * 128; idx += 256) {
            int k = idx >> 7, c = idx & 127;
            Ws[k * 128 + c] = W[(size_t)(kc + k) * DH + c];
        }
        __syncthreads();

        #pragma unroll 4
        for (int k = 0; k < 32; k++) {
            float h[8], w[8];
            #pragma unroll
            for (int i = 0; i < 8; i++) h[i] = HsT[k * 129 + ty * 8 + i];
            float4 w0 = *(const float4*)&Ws[k * 128 + tx * 8];
            float4 w1 = *(const float4*)&Ws[k * 128 + tx * 8 + 4];
            w[0] = w0.x; w[1] = w0.y; w[2] = w0.z; w[3] = w0.w;
            w[4] = w1.x; w[5] = w1.y; w[6] = w1.z; w[7] = w1.w;
            #pragma unroll
            for (int i = 0; i < 8; i++)
                #pragma unroll
                for (int j = 0; j < 8; j++)
                    acc[i][j] += h[i] * w[j];
        }
    }

    float4 b0 = *(const float4*)&b[tx * 8];
    float4 b1 = *(const float4*)&b[tx * 8 + 4];
    #pragma unroll
    for (int i = 0; i < 8; i++) {
        int r = row0 + ty * 8 + i;
        float4 o0, o1;
        o0.x = acc[i][0] + b0.x; o0.y = acc[i][1] + b0.y;
        o0.z = acc[i][2] + b0.z; o0.w = acc[i][3] + b0.w;
        o1.x = acc[i][4] + b1.x; o1.y = acc[i][5] + b1.y;
        o1.z = acc[i][6] + b1.z; o1.w = acc[i][7] + b1.w;
        *(float4*)&outp[(size_t)r * DH + tx * 8]     = o0;
        *(float4*)&outp[(size_t)r * DH + tx * 8 + 4] = o1;
    }
}

// ---------------------------------------------------------------------------
// Kernel 2: fused flash attention + residual.
// Block = 256 threads (16x16), BQ=64 query rows, streams 256 key tiles of 64.
// Thread (ty,tx): S microtile rows ty*4..+3, cols tx*4..+3;
//                 O microtile rows ty*4..+3, cols tx*16..+15.
// ---------------------------------------------------------------------------
#define ATTN_SMEM_FLOATS (128 * QK_PAD * 2 + BK * TT + BQ * P_PAD)
#define ATTN_SMEM_BYTES  (ATTN_SMEM_FLOATS * 4)

__global__ __launch_bounds__(256, 1)
void attn_kernel(const float* __restrict__ H, float* __restrict__ out) {
    extern __shared__ float sm[];
    float* Qst = sm;                       // [128][QK_PAD] k-major
    float* Kst = Qst + 128 * QK_PAD;       // [128][QK_PAD] k-major
    float* Hs  = Kst + 128 * QK_PAD;       // [64][256]
    float* Ps  = Hs + BK * TT;             // [64][P_PAD]

    const int tid = threadIdx.x;
    const int ty = tid >> 4;               // 0..15
    const int tx = tid & 15;               // 0..15
    const int q0 = blockIdx.x * BQ;

    // load Q block k-major: Qst[k][r] = Q[q0+r][k]
    for (int idx = tid; idx < BQ * DH; idx += 256) {
        int r = idx >> 7, k = idx & 127;
        Qst[k * QK_PAD + r] = g_Q[(size_t)(q0 + r) * DH + k];
    }

    float m[4], l[4], O[4][16];
    #pragma unroll
    for (int i = 0; i < 4; i++) {
        m[i] = -1e30f; l[i] = 0.f;
        #pragma unroll
        for (int c = 0; c < 16; c++) O[i][c] = 0.f;
    }

    const float SCALE = 0.08838834764831845f;  // 1/sqrt(128)

    for (int kt = 0; kt < NN / BK; kt++) {
        const int k0 = kt * BK;
        __syncthreads();   // previous iteration done with Kst/Hs (also covers Qst fill on kt=0)

        // load K tile k-major
        for (int idx = tid; idx < BK * DH; idx += 256) {
            int r = idx >> 7, k = idx & 127;
            Kst[k * QK_PAD + r] = g_K[(size_t)(k0 + r) * DH + k];
        }
        // load H tile (vectorized)
        for (int idx = tid; idx < BK * (TT / 4); idx += 256) {
            int j = idx >> 6, c4 = idx & 63;
            ((float4*)Hs)[j * (TT / 4) + c4] =
                ((const float4*)(H + (size_t)(k0 + j) * TT))[c4];
        }
        __syncthreads();

        // ---- S = Q K^T (4x4 per thread) ----
        float s[4][4];
        #pragma unroll
        for (int i = 0; i < 4; i++)
            #pragma unroll
            for (int j = 0; j < 4; j++) s[i][j] = 0.f;

        #pragma unroll 4
        for (int k = 0; k < DH; k++) {
            float4 qv = *(const float4*)&Qst[k * QK_PAD + ty * 4];
            float4 kv = *(const float4*)&Kst[k * QK_PAD + tx * 4];
            float q[4] = {qv.x, qv.y, qv.z, qv.w};
            float kk[4] = {kv.x, kv.y, kv.z, kv.w};
            #pragma unroll
            for (int i = 0; i < 4; i++)
                #pragma unroll
                for (int j = 0; j < 4; j++)
                    s[i][j] += q[i] * kk[j];
        }

        // scale + zero diagonal (pre-scale zeroing == post-scale zeroing: 0/sqrt=0)
        #pragma unroll
        for (int i = 0; i < 4; i++) {
            int gr = q0 + ty * 4 + i;
            #pragma unroll
            for (int j = 0; j < 4; j++) {
                int gc = k0 + tx * 4 + j;
                float v = s[i][j] * SCALE;
                s[i][j] = (gr == gc) ? 0.f : v;
            }
        }

        // ---- online softmax (reductions over 16-lane tx groups) ----
        float p[4][4], alpha[4];
        #pragma unroll
        for (int i = 0; i < 4; i++) {
            float rm = fmaxf(fmaxf(s[i][0], s[i][1]), fmaxf(s[i][2], s[i][3]));
            #pragma unroll
            for (int off = 8; off; off >>= 1)
                rm = fmaxf(rm, __shfl_xor_sync(0xffffffffu, rm, off));
            float mnew = fmaxf(m[i], rm);
            alpha[i] = __expf(m[i] - mnew);
            m[i] = mnew;
            float rs = 0.f;
            #pragma unroll
            for (int j = 0; j < 4; j++) {
                p[i][j] = __expf(s[i][j] - mnew);
                rs += p[i][j];
            }
            #pragma unroll
            for (int off = 8; off; off >>= 1)
                rs += __shfl_xor_sync(0xffffffffu, rs, off);
            l[i] = l[i] * alpha[i] + rs;
        }

        // publish P to smem (row r lives entirely in this half-warp)
        #pragma unroll
        for (int i = 0; i < 4; i++) {
            float4 pv = make_float4(p[i][0], p[i][1], p[i][2], p[i][3]);
            *(float4*)&Ps[(ty * 4 + i) * P_PAD + tx * 4] = pv;
        }

        // rescale O
        #pragma unroll
        for (int i = 0; i < 4; i++)
            #pragma unroll
            for (int c = 0; c < 16; c++) O[i][c] *= alpha[i];

        __syncwarp();   // P exchange is intra-half-warp only

        // ---- O += P @ H_tile ----
        #pragma unroll 2
        for (int j = 0; j < BK; j++) {
            float pv[4];
            #pragma unroll
            for (int i = 0; i < 4; i++)
                pv[i] = Ps[(ty * 4 + i) * P_PAD + j];
            const float* hrow = &Hs[j * TT + tx * 16];
            float4 h0 = *(const float4*)(hrow);
            float4 h1 = *(const float4*)(hrow + 4);
            float4 h2 = *(const float4*)(hrow + 8);
            float4 h3 = *(const float4*)(hrow + 12);
            float hv[16] = {h0.x, h0.y, h0.z, h0.w, h1.x, h1.y, h1.z, h1.w,
                            h2.x, h2.y, h2.z, h2.w, h3.x, h3.y, h3.z, h3.w};
            #pragma unroll
            for (int i = 0; i < 4; i++)
                #pragma unroll
                for (int c = 0; c < 16; c++)
                    O[i][c] += pv[i] * hv[c];
        }
        __syncwarp();
    }

    // ---- epilogue: out = O/l + H ----
    #pragma unroll
    for (int i = 0; i < 4; i++) {
        int r = q0 + ty * 4 + i;
        float inv = 1.0f / l[i];
        #pragma unroll
        for (int g = 0; g < 4; g++) {
            int c = tx * 16 + g * 4;
            float4 hv = *(const float4*)&H[(size_t)r * TT + c];
            float4 o;
            o.x = O[i][g * 4 + 0] * inv + hv.x;
            o.y = O[i][g * 4 + 1] * inv + hv.y;
            o.z = O[i][g * 4 + 2] * inv + hv.z;
            o.w = O[i][g * 4 + 3] * inv + hv.w;
            *(float4*)&out[(size_t)r * TT + c] = o;
        }
    }
}

// ---------------------------------------------------------------------------
extern "C" void kernel_launch(void* const* d_in, const int* in_sizes, int n_in,
                              void* d_out, int out_size) {
    const float* H  = (const float*)d_in[0];
    const float* Wq = (const float*)d_in[1];
    const float* bq = (const float*)d_in[2];
    const float* Wk = (const float*)d_in[3];
    const float* bk = (const float*)d_in[4];
    float* out = (float*)d_out;

    cudaFuncSetAttribute(attn_kernel,
                         cudaFuncAttributeMaxDynamicSharedMemorySize,
                         ATTN_SMEM_BYTES);

    qk_kernel<<<dim3(NN / 128, 2), 256>>>(H, Wq, bq, Wk, bk);
    attn_kernel<<<NN / BQ, 256, ATTN_SMEM_BYTES>>>(H, out);
}

// round 3
// speedup vs baseline: 11.1367x; 11.1367x over previous
#include <cuda_runtime.h>
#include <cuda_bf16.h>
#include <cstdint>

#define NN 16384
#define DH 128
#define TT 256
#define SCALE 0.08838834764831845f   // 1/sqrt(128)

#define BM 64
#define BN 128

// smem layout (bytes)
#define KS_STRIDE 272                      // 128 bf16 + 8 pad
#define HS_STRIDE 528                      // 256 bf16 + 8 pad
#define PS_STRIDE 272
#define OFF_K 0
#define OFF_H (128 * KS_STRIDE)            // 34816
#define OFF_P (OFF_H + 128 * HS_STRIDE)    // 102400
#define OFF_L (OFF_P + 64 * PS_STRIDE)     // 119808
#define ATTN_SMEM (OFF_L + 2 * 64 * 4)     // 120320

// device-global scratch (allocation-guard safe)
__device__ __nv_bfloat16 g_Qb[NN * DH];          // Q*SCALE bf16
__device__ __nv_bfloat16 g_Kb[NN * DH];          // K bf16
__device__ __nv_bfloat16 g_Hb[(size_t)NN * TT];  // H bf16 (row-major)

// ===========================================================================
// helpers (all sm_80-baseline PTX: portable under compute_103)
// ===========================================================================
__device__ __forceinline__ uint32_t smem_u32(const void* p) {
    uint32_t a;
    asm("{ .reg .u64 t; cvta.to.shared.u64 t, %1; cvt.u32.u64 %0, t; }"
        : "=r"(a) : "l"(p));
    return a;
}
__device__ __forceinline__ void ldsm_x4(uint32_t& r0, uint32_t& r1,
                                        uint32_t& r2, uint32_t& r3, uint32_t a) {
    asm volatile("ldmatrix.sync.aligned.m8n8.x4.shared.b16 {%0,%1,%2,%3}, [%4];"
                 : "=r"(r0), "=r"(r1), "=r"(r2), "=r"(r3) : "r"(a));
}
__device__ __forceinline__ void ldsm_x4_t(uint32_t& r0, uint32_t& r1,
                                          uint32_t& r2, uint32_t& r3, uint32_t a) {
    asm volatile("ldmatrix.sync.aligned.m8n8.x4.trans.shared.b16 {%0,%1,%2,%3}, [%4];"
                 : "=r"(r0), "=r"(r1), "=r"(r2), "=r"(r3) : "r"(a));
}
__device__ __forceinline__ void mma16816(float* d, const uint32_t* a,
                                         uint32_t b0, uint32_t b1) {
    asm volatile("mma.sync.aligned.m16n8k16.row.col.f32.bf16.bf16.f32 "
                 "{%0,%1,%2,%3},{%4,%5,%6,%7},{%8,%9},{%0,%1,%2,%3};"
                 : "+f"(d[0]), "+f"(d[1]), "+f"(d[2]), "+f"(d[3])
                 : "r"(a[0]), "r"(a[1]), "r"(a[2]), "r"(a[3]), "r"(b0), "r"(b1));
}

// ===========================================================================
// Kernel 1: Q = (H Wq + bq)*SCALE -> bf16 ; K = H Wk + bk -> bf16
// ===========================================================================
__global__ __launch_bounds__(256)
void qk_kernel(const float* __restrict__ H,
               const float* __restrict__ Wq, const float* __restrict__ bq,
               const float* __restrict__ Wk, const float* __restrict__ bk) {
    __shared__ float HsT[32 * 129];
    __shared__ float Ws[32 * 128];

    const float* W = blockIdx.y ? Wk : Wq;
    const float* b = blockIdx.y ? bk : bq;
    __nv_bfloat16* outp = blockIdx.y ? g_Kb : g_Qb;
    const float osc = blockIdx.y ? 1.0f : SCALE;

    const int tid = threadIdx.x;
    const int ty = tid >> 4, tx = tid & 15;
    const int row0 = blockIdx.x * 128;

    float acc[8][8];
    #pragma unroll
    for (int i = 0; i < 8; i++)
        #pragma unroll
        for (int j = 0; j < 8; j++) acc[i][j] = 0.f;

    for (int kc = 0; kc < TT; kc += 32) {
        __syncthreads();
        #pragma unroll
        for (int idx = tid; idx < 128 * 32; idx += 256) {
            int r = idx >> 5, k = idx & 31;
            HsT[k * 129 + r] = H[(size_t)(row0 + r) * TT + kc + k];
        }
        #pragma unroll
        for (int idx = tid; idx < 32 * 128; idx += 256) {
            int k = idx >> 7, c = idx & 127;
            Ws[k * 128 + c] = W[(size_t)(kc + k) * DH + c];
        }
        __syncthreads();
        #pragma unroll 4
        for (int k = 0; k < 32; k++) {
            float h[8], w[8];
            #pragma unroll
            for (int i = 0; i < 8; i++) h[i] = HsT[k * 129 + ty * 8 + i];
            float4 w0 = *(const float4*)&Ws[k * 128 + tx * 8];
            float4 w1 = *(const float4*)&Ws[k * 128 + tx * 8 + 4];
            w[0]=w0.x; w[1]=w0.y; w[2]=w0.z; w[3]=w0.w;
            w[4]=w1.x; w[5]=w1.y; w[6]=w1.z; w[7]=w1.w;
            #pragma unroll
            for (int i = 0; i < 8; i++)
                #pragma unroll
                for (int j = 0; j < 8; j++)
                    acc[i][j] += h[i] * w[j];
        }
    }

    float bb[8];
    {
        float4 b0 = *(const float4*)&b[tx * 8];
        float4 b1 = *(const float4*)&b[tx * 8 + 4];
        bb[0]=b0.x; bb[1]=b0.y; bb[2]=b0.z; bb[3]=b0.w;
        bb[4]=b1.x; bb[5]=b1.y; bb[6]=b1.z; bb[7]=b1.w;
    }
    #pragma unroll
    for (int i = 0; i < 8; i++) {
        int r = row0 + ty * 8 + i;
        __nv_bfloat16 t8[8];
        #pragma unroll
        for (int j = 0; j < 8; j++)
            t8[j] = __float2bfloat16((acc[i][j] + bb[j]) * osc);
        *(uint4*)&outp[(size_t)r * DH + tx * 8] = *(const uint4*)t8;
    }
}

// ===========================================================================
// Kernel 2: H -> bf16 (row-major, no transpose)
// ===========================================================================
__global__ __launch_bounds__(256)
void hconv_kernel(const float* __restrict__ H) {
    size_t i = (size_t)blockIdx.x * 256 + threadIdx.x;
    float4 v = ((const float4*)H)[i];
    __nv_bfloat162 a = __floats2bfloat162_rn(v.x, v.y);
    __nv_bfloat162 b = __floats2bfloat162_rn(v.z, v.w);
    uint2 o;
    o.x = *(uint32_t*)&a;
    o.y = *(uint32_t*)&b;
    ((uint2*)g_Hb)[i] = o;
}

// ===========================================================================
// Kernel 3: flash attention via mma.sync bf16.
// 256 CTAs x 256 threads. Warp (wr = wid&3, wc = wid>>2):
//   MMA1: S[16 rows, 64 cols(wc)] = Q @ K^T
//   exp -> P bf16 -> smem exchange
//   MMA2: O[16 rows, 128 cols(wc)] += P[16,128] @ H[128,128]
// ===========================================================================
__global__ __launch_bounds__(256, 1)
void attn3_kernel(const float* __restrict__ H, float* __restrict__ out) {
    extern __shared__ char sm[];
    const uint32_t sb = smem_u32(sm);
    const int tid = threadIdx.x;
    const int wid = tid >> 5, lane = tid & 31;
    const int wr = wid & 3, wc = wid >> 2;
    const int g = lane >> 2, t = lane & 3;
    const int bl = lane >> 3, rl = lane & 7;   // ldmatrix block id / row-in-block
    const int q0 = blockIdx.x * BM;

    // ---- load Q tile (64 x 128 bf16) into Ps region, build persistent A frags
    for (int i = tid; i < BM * 16; i += 256) {
        int r = i >> 4, c = i & 15;
        uint4 v = *(const uint4*)(g_Qb + (size_t)(q0 + r) * DH + c * 8);
        *(uint4*)(sm + OFF_P + r * PS_STRIDE + c * 16) = v;
    }
    __syncthreads();

    uint32_t aq[8][4];
    {
        int m = wr * 16 + rl + ((bl & 1) ? 8 : 0);
        #pragma unroll
        for (int s = 0; s < 8; s++) {
            uint32_t addr = sb + OFF_P + m * PS_STRIDE + s * 32 + ((bl & 2) ? 16 : 0);
            ldsm_x4(aq[s][0], aq[s][1], aq[s][2], aq[s][3], addr);
        }
    }

    float oacc[16][4];
    #pragma unroll
    for (int i = 0; i < 16; i++)
        #pragma unroll
        for (int j = 0; j < 4; j++) oacc[i][j] = 0.f;
    float lsum0 = 0.f, lsum1 = 0.f;
    const int diag_kt = q0 >> 7;

    for (int kt = 0; kt < NN / BN; kt++) {
        const int k0 = kt * BN;

        // ---- load K tile [128,128] and H tile [128,256] (bf16, padded rows)
        for (int i = tid; i < 128 * 16; i += 256) {
            int r = i >> 4, c = i & 15;
            uint4 v = *(const uint4*)(g_Kb + (size_t)(k0 + r) * DH + c * 8);
            *(uint4*)(sm + OFF_K + r * KS_STRIDE + c * 16) = v;
        }
        for (int i = tid; i < 128 * 32; i += 256) {
            int r = i >> 5, c = i & 31;
            uint4 v = *(const uint4*)(g_Hb + (size_t)(k0 + r) * TT + c * 8);
            *(uint4*)(sm + OFF_H + r * HS_STRIDE + c * 16) = v;
        }
        __syncthreads();

        // ---- MMA1: S = Q @ K^T  (warp cols wc*64 .. +63)
        float sacc[8][4];
        #pragma unroll
        for (int i = 0; i < 8; i++)
            #pragma unroll
            for (int j = 0; j < 4; j++) sacc[i][j] = 0.f;
        {
            int nrow = wc * 64 + rl + ((bl & 2) ? 8 : 0);
            int kc = (bl & 1) ? 16 : 0;
            #pragma unroll
            for (int s = 0; s < 8; s++) {
                #pragma unroll
                for (int jj = 0; jj < 4; jj++) {
                    uint32_t addr = sb + OFF_K + (nrow + jj * 16) * KS_STRIDE + s * 32 + kc;
                    uint32_t b0, b1, b2, b3;
                    ldsm_x4(b0, b1, b2, b3, addr);
                    mma16816(sacc[2 * jj], aq[s], b0, b1);
                    mma16816(sacc[2 * jj + 1], aq[s], b2, b3);
                }
            }
        }

        // ---- exp + diag + row sums + publish P (bf16) to smem
        {
            const int row0 = wr * 16 + g;
            const bool dt = (kt == diag_kt);
            const int grow0 = q0 + row0, grow1 = grow0 + 8;
            #pragma unroll
            for (int j = 0; j < 8; j++) {
                int col = wc * 64 + j * 8 + 2 * t;
                int gcol = k0 + col;
                float p0 = __expf(sacc[j][0]);
                float p1 = __expf(sacc[j][1]);
                float p2 = __expf(sacc[j][2]);
                float p3 = __expf(sacc[j][3]);
                if (dt) {   // diagonal logit forced to 0 -> p = 1
                    if (grow0 == gcol)     p0 = 1.f;
                    if (grow0 == gcol + 1) p1 = 1.f;
                    if (grow1 == gcol)     p2 = 1.f;
                    if (grow1 == gcol + 1) p3 = 1.f;
                }
                lsum0 += p0 + p1;
                lsum1 += p2 + p3;
                __nv_bfloat162 v0 = __floats2bfloat162_rn(p0, p1);
                __nv_bfloat162 v1 = __floats2bfloat162_rn(p2, p3);
                *(uint32_t*)(sm + OFF_P + row0 * PS_STRIDE + col * 2) = *(uint32_t*)&v0;
                *(uint32_t*)(sm + OFF_P + (row0 + 8) * PS_STRIDE + col * 2) = *(uint32_t*)&v1;
            }
        }
        __syncthreads();

        // ---- MMA2: O += P @ H  (warp cols wc*128 .. +127)
        {
            int am = wr * 16 + rl + ((bl & 1) ? 8 : 0);
            int akc = (bl & 2) ? 16 : 0;
            int bk = rl + ((bl & 1) ? 8 : 0);
            int bn = (bl & 2) ? 8 : 0;
            #pragma unroll
            for (int s2 = 0; s2 < 8; s2++) {
                uint32_t av[4];
                ldsm_x4(av[0], av[1], av[2], av[3],
                        sb + OFF_P + am * PS_STRIDE + s2 * 32 + akc);
                #pragma unroll
                for (int jj = 0; jj < 8; jj++) {
                    int n0 = wc * 128 + jj * 16;
                    uint32_t addr = sb + OFF_H + (s2 * 16 + bk) * HS_STRIDE + (n0 + bn) * 2;
                    uint32_t b0, b1, b2, b3;
                    ldsm_x4_t(b0, b1, b2, b3, addr);
                    mma16816(oacc[2 * jj], av, b0, b1);
                    mma16816(oacc[2 * jj + 1], av, b2, b3);
                }
            }
        }
        __syncthreads();   // MMA2 reads done before next tile overwrites Ks/Hs/Ps
    }

    // ---- row-sum reduce: quad shuffle, then cross-wc via smem
    lsum0 += __shfl_xor_sync(0xffffffffu, lsum0, 1);
    lsum0 += __shfl_xor_sync(0xffffffffu, lsum0, 2);
    lsum1 += __shfl_xor_sync(0xffffffffu, lsum1, 1);
    lsum1 += __shfl_xor_sync(0xffffffffu, lsum1, 2);
    float* Ls = (float*)(sm + OFF_L);
    if (t == 0) {
        Ls[wc * 64 + wr * 16 + g] = lsum0;
        Ls[wc * 64 + wr * 16 + g + 8] = lsum1;
    }
    __syncthreads();

    const int r0 = wr * 16 + g;
    const float inv0 = 1.f / (Ls[r0] + Ls[64 + r0]);
    const float inv1 = 1.f / (Ls[r0 + 8] + Ls[64 + r0 + 8]);
    const int grow0 = q0 + r0;

    // ---- epilogue: out = O/l + H
    #pragma unroll
    for (int j2 = 0; j2 < 16; j2++) {
        int col = wc * 128 + j2 * 8 + 2 * t;
        float2 h0 = *(const float2*)(H + (size_t)grow0 * TT + col);
        float2 h1 = *(const float2*)(H + (size_t)(grow0 + 8) * TT + col);
        float2 o0, o1;
        o0.x = oacc[j2][0] * inv0 + h0.x;
        o0.y = oacc[j2][1] * inv0 + h0.y;
        o1.x = oacc[j2][2] * inv1 + h1.x;
        o1.y = oacc[j2][3] * inv1 + h1.y;
        *(float2*)(out + (size_t)grow0 * TT + col) = o0;
        *(float2*)(out + (size_t)(grow0 + 8) * TT + col) = o1;
    }
}

// ===========================================================================
extern "C" void kernel_launch(void* const* d_in, const int* in_sizes, int n_in,
                              void* d_out, int out_size) {
    const float* H  = (const float*)d_in[0];
    const float* Wq = (const float*)d_in[1];
    const float* bq = (const float*)d_in[2];
    const float* Wk = (const float*)d_in[3];
    const float* bk = (const float*)d_in[4];
    float* out = (float*)d_out;

    cudaFuncSetAttribute(attn3_kernel,
                         cudaFuncAttributeMaxDynamicSharedMemorySize, ATTN_SMEM);

    qk_kernel<<<dim3(NN / 128, 2), 256>>>(H, Wq, bq, Wk, bk);
    hconv_kernel<<<(NN * TT / 4) / 256, 256>>>(H);
    attn3_kernel<<<NN / BM, 256, ATTN_SMEM>>>(H, out);
}

// round 4
// speedup vs baseline: 13.5694x; 1.2184x over previous
#include <cuda_runtime.h>
#include <cuda_bf16.h>
#include <cstdint>

#define NN 16384
#define DH 128
#define TT 256
#define SCALE 0.08838834764831845f   // 1/sqrt(128)

#define BM 64
#define BN 128
#define NT (NN / BN)

// smem layout (bytes) — double-buffered K/H
#define KS_STRIDE 272                      // 128 bf16 + 8 pad
#define HS_STRIDE 528                      // 256 bf16 + 8 pad
#define PS_STRIDE 272
#define KBYTES (128 * KS_STRIDE)           // 34816
#define HBYTES (128 * HS_STRIDE)           // 67584
#define OFF_K 0                            // 2 stages
#define OFF_H (2 * KBYTES)                 // 69632, 2 stages
#define OFF_P (OFF_H + 2 * HBYTES)         // 204800
#define OFF_L (OFF_P + 64 * PS_STRIDE)     // 222208
#define ATTN_SMEM (OFF_L + 2 * 64 * 4)     // 222720

// device-global scratch (allocation-guard safe)
__device__ __nv_bfloat16 g_Qb[NN * DH];          // Q*SCALE bf16
__device__ __nv_bfloat16 g_Kb[NN * DH];          // K bf16
__device__ __nv_bfloat16 g_Hb[(size_t)NN * TT];  // H bf16 (row-major)

// ===========================================================================
// helpers (sm_80-baseline PTX: portable under compute_103)
// ===========================================================================
__device__ __forceinline__ uint32_t smem_u32(const void* p) {
    uint32_t a;
    asm("{ .reg .u64 t; cvta.to.shared.u64 t, %1; cvt.u32.u64 %0, t; }"
        : "=r"(a) : "l"(p));
    return a;
}
__device__ __forceinline__ void ldsm_x4(uint32_t& r0, uint32_t& r1,
                                        uint32_t& r2, uint32_t& r3, uint32_t a) {
    asm volatile("ldmatrix.sync.aligned.m8n8.x4.shared.b16 {%0,%1,%2,%3}, [%4];"
                 : "=r"(r0), "=r"(r1), "=r"(r2), "=r"(r3) : "r"(a));
}
__device__ __forceinline__ void ldsm_x4_t(uint32_t& r0, uint32_t& r1,
                                          uint32_t& r2, uint32_t& r3, uint32_t a) {
    asm volatile("ldmatrix.sync.aligned.m8n8.x4.trans.shared.b16 {%0,%1,%2,%3}, [%4];"
                 : "=r"(r0), "=r"(r1), "=r"(r2), "=r"(r3) : "r"(a));
}
__device__ __forceinline__ void mma16816(float* d, const uint32_t* a,
                                         uint32_t b0, uint32_t b1) {
    asm volatile("mma.sync.aligned.m16n8k16.row.col.f32.bf16.bf16.f32 "
                 "{%0,%1,%2,%3},{%4,%5,%6,%7},{%8,%9},{%0,%1,%2,%3};"
                 : "+f"(d[0]), "+f"(d[1]), "+f"(d[2]), "+f"(d[3])
                 : "r"(a[0]), "r"(a[1]), "r"(a[2]), "r"(a[3]), "r"(b0), "r"(b1));
}
__device__ __forceinline__ void cp16(uint32_t dst, const void* src) {
    asm volatile("cp.async.cg.shared.global [%0], [%1], 16;"
                 :: "r"(dst), "l"(src) : "memory");
}
__device__ __forceinline__ void cp_commit() {
    asm volatile("cp.async.commit_group;" ::: "memory");
}
__device__ __forceinline__ void cp_wait1() {
    asm volatile("cp.async.wait_group 1;" ::: "memory");
}
__device__ __forceinline__ void cp_wait0() {
    asm volatile("cp.async.wait_group 0;" ::: "memory");
}

// ===========================================================================
// Kernel 1: Q = (H Wq + bq)*SCALE -> bf16 ; K = H Wk + bk -> bf16
// ===========================================================================
__global__ __launch_bounds__(256)
void qk_kernel(const float* __restrict__ H,
               const float* __restrict__ Wq, const float* __restrict__ bq,
               const float* __restrict__ Wk, const float* __restrict__ bk) {
    __shared__ float HsT[32 * 129];
    __shared__ float Ws[32 * 128];

    const float* W = blockIdx.y ? Wk : Wq;
    const float* b = blockIdx.y ? bk : bq;
    __nv_bfloat16* outp = blockIdx.y ? g_Kb : g_Qb;
    const float osc = blockIdx.y ? 1.0f : SCALE;

    const int tid = threadIdx.x;
    const int ty = tid >> 4, tx = tid & 15;
    const int row0 = blockIdx.x * 128;

    float acc[8][8];
    #pragma unroll
    for (int i = 0; i < 8; i++)
        #pragma unroll
        for (int j = 0; j < 8; j++) acc[i][j] = 0.f;

    for (int kc = 0; kc < TT; kc += 32) {
        __syncthreads();
        #pragma unroll
        for (int idx = tid; idx < 128 * 32; idx += 256) {
            int r = idx >> 5, k = idx & 31;
            HsT[k * 129 + r] = H[(size_t)(row0 + r) * TT + kc + k];
        }
        #pragma unroll
        for (int idx = tid; idx < 32 * 128; idx += 256) {
            int k = idx >> 7, c = idx & 127;
            Ws[k * 128 + c] = W[(size_t)(kc + k) * DH + c];
        }
        __syncthreads();
        #pragma unroll 4
        for (int k = 0; k < 32; k++) {
            float h[8], w[8];
            #pragma unroll
            for (int i = 0; i < 8; i++) h[i] = HsT[k * 129 + ty * 8 + i];
            float4 w0 = *(const float4*)&Ws[k * 128 + tx * 8];
            float4 w1 = *(const float4*)&Ws[k * 128 + tx * 8 + 4];
            w[0]=w0.x; w[1]=w0.y; w[2]=w0.z; w[3]=w0.w;
            w[4]=w1.x; w[5]=w1.y; w[6]=w1.z; w[7]=w1.w;
            #pragma unroll
            for (int i = 0; i < 8; i++)
                #pragma unroll
                for (int j = 0; j < 8; j++)
                    acc[i][j] += h[i] * w[j];
        }
    }

    float bb[8];
    {
        float4 b0 = *(const float4*)&b[tx * 8];
        float4 b1 = *(const float4*)&b[tx * 8 + 4];
        bb[0]=b0.x; bb[1]=b0.y; bb[2]=b0.z; bb[3]=b0.w;
        bb[4]=b1.x; bb[5]=b1.y; bb[6]=b1.z; bb[7]=b1.w;
    }
    #pragma unroll
    for (int i = 0; i < 8; i++) {
        int r = row0 + ty * 8 + i;
        __nv_bfloat16 t8[8];
        #pragma unroll
        for (int j = 0; j < 8; j++)
            t8[j] = __float2bfloat16((acc[i][j] + bb[j]) * osc);
        *(uint4*)&outp[(size_t)r * DH + tx * 8] = *(const uint4*)t8;
    }
}

// ===========================================================================
// Kernel 2: H -> bf16 (row-major)
// ===========================================================================
__global__ __launch_bounds__(256)
void hconv_kernel(const float* __restrict__ H) {
    size_t i = (size_t)blockIdx.x * 256 + threadIdx.x;
    float4 v = ((const float4*)H)[i];
    __nv_bfloat162 a = __floats2bfloat162_rn(v.x, v.y);
    __nv_bfloat162 b = __floats2bfloat162_rn(v.z, v.w);
    uint2 o;
    o.x = *(uint32_t*)&a;
    o.y = *(uint32_t*)&b;
    ((uint2*)g_Hb)[i] = o;
}

// ===========================================================================
// Kernel 3: flash attention, mma.sync bf16, cp.async double-buffered tiles.
// ===========================================================================
__device__ __forceinline__ void issue_tile(uint32_t sb, int tid, int k0, int stage) {
    // K tile: 128 x 128 bf16
    {
        const char* src = (const char*)(g_Kb + (size_t)k0 * DH);
        uint32_t dstb = sb + OFF_K + stage * KBYTES;
        #pragma unroll
        for (int i = tid; i < 2048; i += 256) {
            int r = i >> 4, c = i & 15;
            cp16(dstb + r * KS_STRIDE + c * 16, src + r * 256 + c * 16);
        }
    }
    // H tile: 128 x 256 bf16
    {
        const char* src = (const char*)(g_Hb + (size_t)k0 * TT);
        uint32_t dstb = sb + OFF_H + stage * HBYTES;
        #pragma unroll
        for (int i = tid; i < 4096; i += 256) {
            int r = i >> 5, c = i & 31;
            cp16(dstb + r * HS_STRIDE + c * 16, src + r * 512 + c * 16);
        }
    }
}

__global__ __launch_bounds__(256, 1)
void attn4_kernel(const float* __restrict__ H, float* __restrict__ out) {
    extern __shared__ char sm[];
    const uint32_t sb = smem_u32(sm);
    const int tid = threadIdx.x;
    const int wid = tid >> 5, lane = tid & 31;
    const int wr = wid & 3, wc = wid >> 2;
    const int g = lane >> 2, t = lane & 3;
    const int bl = lane >> 3, rl = lane & 7;
    const int q0 = blockIdx.x * BM;

    // prefetch tile 0 while we set up Q
    issue_tile(sb, tid, 0, 0);
    cp_commit();

    // ---- load Q tile (64 x 128 bf16) into P region, build persistent A frags
    for (int i = tid; i < BM * 16; i += 256) {
        int r = i >> 4, c = i & 15;
        uint4 v = *(const uint4*)(g_Qb + (size_t)(q0 + r) * DH + c * 8);
        *(uint4*)(sm + OFF_P + r * PS_STRIDE + c * 16) = v;
    }
    __syncthreads();

    uint32_t aq[8][4];
    {
        int m = wr * 16 + rl + ((bl & 1) ? 8 : 0);
        #pragma unroll
        for (int s = 0; s < 8; s++) {
            uint32_t addr = sb + OFF_P + m * PS_STRIDE + s * 32 + ((bl & 2) ? 16 : 0);
            ldsm_x4(aq[s][0], aq[s][1], aq[s][2], aq[s][3], addr);
        }
    }

    float oacc[16][4];
    #pragma unroll
    for (int i = 0; i < 16; i++)
        #pragma unroll
        for (int j = 0; j < 4; j++) oacc[i][j] = 0.f;
    float lsum0 = 0.f, lsum1 = 0.f;
    const int diag_kt = q0 >> 7;

    for (int kt = 0; kt < NT; kt++) {
        const int k0 = kt * BN;
        const int cur = kt & 1;

        // prefetch next tile into the other stage (safe: end-of-prev-iter sync
        // guarantees nobody still reads that stage)
        if (kt + 1 < NT) {
            issue_tile(sb, tid, (kt + 1) * BN, cur ^ 1);
            cp_commit();
            cp_wait1();
        } else {
            cp_wait0();
        }
        __syncthreads();   // tile kt visible to all warps

        const uint32_t kbase = sb + OFF_K + cur * KBYTES;
        const uint32_t hbase = sb + OFF_H + cur * HBYTES;

        // ---- MMA1: S = Q @ K^T  (warp cols wc*64 .. +63)
        float sacc[8][4];
        #pragma unroll
        for (int i = 0; i < 8; i++)
            #pragma unroll
            for (int j = 0; j < 4; j++) sacc[i][j] = 0.f;
        {
            int nrow = wc * 64 + rl + ((bl & 2) ? 8 : 0);
            int kc = (bl & 1) ? 16 : 0;
            #pragma unroll
            for (int s = 0; s < 8; s++) {
                #pragma unroll
                for (int jj = 0; jj < 4; jj++) {
                    uint32_t addr = kbase + (nrow + jj * 16) * KS_STRIDE + s * 32 + kc;
                    uint32_t b0, b1, b2, b3;
                    ldsm_x4(b0, b1, b2, b3, addr);
                    mma16816(sacc[2 * jj], aq[s], b0, b1);
                    mma16816(sacc[2 * jj + 1], aq[s], b2, b3);
                }
            }
        }

        // ---- exp + diag + row sums + publish P (bf16)
        {
            const int row0 = wr * 16 + g;
            const bool dt = (kt == diag_kt);
            const int grow0 = q0 + row0, grow1 = grow0 + 8;
            #pragma unroll
            for (int j = 0; j < 8; j++) {
                int col = wc * 64 + j * 8 + 2 * t;
                int gcol = k0 + col;
                float p0 = __expf(sacc[j][0]);
                float p1 = __expf(sacc[j][1]);
                float p2 = __expf(sacc[j][2]);
                float p3 = __expf(sacc[j][3]);
                if (dt) {
                    if (grow0 == gcol)     p0 = 1.f;
                    if (grow0 == gcol + 1) p1 = 1.f;
                    if (grow1 == gcol)     p2 = 1.f;
                    if (grow1 == gcol + 1) p3 = 1.f;
                }
                lsum0 += p0 + p1;
                lsum1 += p2 + p3;
                __nv_bfloat162 v0 = __floats2bfloat162_rn(p0, p1);
                __nv_bfloat162 v1 = __floats2bfloat162_rn(p2, p3);
                *(uint32_t*)(sm + OFF_P + row0 * PS_STRIDE + col * 2) = *(uint32_t*)&v0;
                *(uint32_t*)(sm + OFF_P + (row0 + 8) * PS_STRIDE + col * 2) = *(uint32_t*)&v1;
            }
        }
        __syncthreads();

        // ---- MMA2: O += P @ H  (warp cols wc*128 .. +127)
        {
            int am = wr * 16 + rl + ((bl & 1) ? 8 : 0);
            int akc = (bl & 2) ? 16 : 0;
            int bk = rl + ((bl & 1) ? 8 : 0);
            int bn = (bl & 2) ? 8 : 0;
            #pragma unroll
            for (int s2 = 0; s2 < 8; s2++) {
                uint32_t av[4];
                ldsm_x4(av[0], av[1], av[2], av[3],
                        sb + OFF_P + am * PS_STRIDE + s2 * 32 + akc);
                #pragma unroll
                for (int jj = 0; jj < 8; jj++) {
                    int n0 = wc * 128 + jj * 16;
                    uint32_t addr = hbase + (s2 * 16 + bk) * HS_STRIDE + (n0 + bn) * 2;
                    uint32_t b0, b1, b2, b3;
                    ldsm_x4_t(b0, b1, b2, b3, addr);
                    mma16816(oacc[2 * jj], av, b0, b1);
                    mma16816(oacc[2 * jj + 1], av, b2, b3);
                }
            }
        }
        __syncthreads();   // all reads of stage cur & P done before reuse
    }

    // ---- row-sum reduce
    lsum0 += __shfl_xor_sync(0xffffffffu, lsum0, 1);
    lsum0 += __shfl_xor_sync(0xffffffffu, lsum0, 2);
    lsum1 += __shfl_xor_sync(0xffffffffu, lsum1, 1);
    lsum1 += __shfl_xor_sync(0xffffffffu, lsum1, 2);
    float* Ls = (float*)(sm + OFF_L);
    if (t == 0) {
        Ls[wc * 64 + wr * 16 + g] = lsum0;
        Ls[wc * 64 + wr * 16 + g + 8] = lsum1;
    }
    __syncthreads();

    const int r0 = wr * 16 + g;
    const float inv0 = 1.f / (Ls[r0] + Ls[64 + r0]);
    const float inv1 = 1.f / (Ls[r0 + 8] + Ls[64 + r0 + 8]);
    const int grow0 = q0 + r0;

    // ---- epilogue: out = O/l + H
    #pragma unroll
    for (int j2 = 0; j2 < 16; j2++) {
        int col = wc * 128 + j2 * 8 + 2 * t;
        float2 h0 = *(const float2*)(H + (size_t)grow0 * TT + col);
        float2 h1 = *(const float2*)(H + (size_t)(grow0 + 8) * TT + col);
        float2 o0, o1;
        o0.x = oacc[j2][0] * inv0 + h0.x;
        o0.y = oacc[j2][1] * inv0 + h0.y;
        o1.x = oacc[j2][2] * inv1 + h1.x;
        o1.y = oacc[j2][3] * inv1 + h1.y;
        *(float2*)(out + (size_t)grow0 * TT + col) = o0;
        *(float2*)(out + (size_t)(grow0 + 8) * TT + col) = o1;
    }
}

// ===========================================================================
extern "C" void kernel_launch(void* const* d_in, const int* in_sizes, int n_in,
                              void* d_out, int out_size) {
    const float* H  = (const float*)d_in[0];
    const float* Wq = (const float*)d_in[1];
    const float* bq = (const float*)d_in[2];
    const float* Wk = (const float*)d_in[3];
    const float* bk = (const float*)d_in[4];
    float* out = (float*)d_out;

    cudaFuncSetAttribute(attn4_kernel,
                         cudaFuncAttributeMaxDynamicSharedMemorySize, ATTN_SMEM);

    qk_kernel<<<dim3(NN / 128, 2), 256>>>(H, Wq, bq, Wk, bk);
    hconv_kernel<<<(NN * TT / 4) / 256, 256>>>(H);
    attn4_kernel<<<NN / BM, 256, ATTN_SMEM>>>(H, out);
}

// round 5
// speedup vs baseline: 13.9735x; 1.0298x over previous
#include <cuda_runtime.h>
#include <cuda_bf16.h>
#include <cstdint>

#define NN 16384
#define DH 128
#define TT 256
#define SCALE 0.08838834764831845f               // 1/sqrt(128)
#define QSCALE (0.08838834764831845f * 1.4426950408889634f)  // fold log2(e)

#define BM 64
#define BN 128
#define NT (NN / BN)

// smem layout (bytes) — double-buffered K/H + Q staging + L
#define KS_STRIDE 272                      // 128 bf16 + 8 pad
#define HS_STRIDE 528                      // 256 bf16 + 8 pad
#define PS_STRIDE 272
#define KBYTES (128 * KS_STRIDE)           // 34816
#define HBYTES (128 * HS_STRIDE)           // 67584
#define OFF_K 0                            // 2 stages
#define OFF_H (2 * KBYTES)                 // 69632, 2 stages
#define OFF_Q (OFF_H + 2 * HBYTES)         // 204800 (Q staging, 17408B)
#define OFF_L (OFF_Q + 64 * PS_STRIDE)     // 222208
#define ATTN_SMEM (OFF_L + 2 * 64 * 4)     // 222720
#define OSM_STRIDE 260                     // epilogue O-exchange stride (floats)

// device-global scratch (allocation-guard safe)
__device__ __nv_bfloat16 g_Qb[NN * DH];          // Q*QSCALE bf16
__device__ __nv_bfloat16 g_Kb[NN * DH];          // K bf16
__device__ __nv_bfloat16 g_Hb[(size_t)NN * TT];  // H bf16

// ===========================================================================
// helpers (sm_80-baseline PTX: portable under compute_103)
// ===========================================================================
__device__ __forceinline__ uint32_t smem_u32(const void* p) {
    uint32_t a;
    asm("{ .reg .u64 t; cvta.to.shared.u64 t, %1; cvt.u32.u64 %0, t; }"
        : "=r"(a) : "l"(p));
    return a;
}
__device__ __forceinline__ void ldsm_x4(uint32_t& r0, uint32_t& r1,
                                        uint32_t& r2, uint32_t& r3, uint32_t a) {
    asm volatile("ldmatrix.sync.aligned.m8n8.x4.shared.b16 {%0,%1,%2,%3}, [%4];"
                 : "=r"(r0), "=r"(r1), "=r"(r2), "=r"(r3) : "r"(a));
}
__device__ __forceinline__ void ldsm_x4_t(uint32_t& r0, uint32_t& r1,
                                          uint32_t& r2, uint32_t& r3, uint32_t a) {
    asm volatile("ldmatrix.sync.aligned.m8n8.x4.trans.shared.b16 {%0,%1,%2,%3}, [%4];"
                 : "=r"(r0), "=r"(r1), "=r"(r2), "=r"(r3) : "r"(a));
}
__device__ __forceinline__ void mma16816(float* d, const uint32_t* a,
                                         uint32_t b0, uint32_t b1) {
    asm volatile("mma.sync.aligned.m16n8k16.row.col.f32.bf16.bf16.f32 "
                 "{%0,%1,%2,%3},{%4,%5,%6,%7},{%8,%9},{%0,%1,%2,%3};"
                 : "+f"(d[0]), "+f"(d[1]), "+f"(d[2]), "+f"(d[3])
                 : "r"(a[0]), "r"(a[1]), "r"(a[2]), "r"(a[3]), "r"(b0), "r"(b1));
}
__device__ __forceinline__ void cp16(uint32_t dst, const void* src) {
    asm volatile("cp.async.cg.shared.global [%0], [%1], 16;"
                 :: "r"(dst), "l"(src) : "memory");
}
__device__ __forceinline__ void cp_commit() {
    asm volatile("cp.async.commit_group;" ::: "memory");
}
__device__ __forceinline__ void cp_wait0() {
    asm volatile("cp.async.wait_group 0;" ::: "memory");
}
__device__ __forceinline__ float ex2f(float x) {
    float y;
    asm("ex2.approx.f32 %0, %1;" : "=f"(y) : "f"(x));
    return y;
}
__device__ __forceinline__ uint32_t packbf2(float lo, float hi) {
    __nv_bfloat162 v = __floats2bfloat162_rn(lo, hi);
    return *(uint32_t*)&v;
}

// ===========================================================================
// Kernel 1: Q = (H Wq + bq)*QSCALE -> bf16 ; K = H Wk + bk -> bf16
// ===========================================================================
__global__ __launch_bounds__(256)
void qk_kernel(const float* __restrict__ H,
               const float* __restrict__ Wq, const float* __restrict__ bq,
               const float* __restrict__ Wk, const float* __restrict__ bk) {
    __shared__ float HsT[32 * 129];
    __shared__ float Ws[32 * 128];

    const float* W = blockIdx.y ? Wk : Wq;
    const float* b = blockIdx.y ? bk : bq;
    __nv_bfloat16* outp = blockIdx.y ? g_Kb : g_Qb;
    const float osc = blockIdx.y ? 1.0f : QSCALE;

    const int tid = threadIdx.x;
    const int ty = tid >> 4, tx = tid & 15;
    const int row0 = blockIdx.x * 128;

    float acc[8][8];
    #pragma unroll
    for (int i = 0; i < 8; i++)
        #pragma unroll
        for (int j = 0; j < 8; j++) acc[i][j] = 0.f;

    for (int kc = 0; kc < TT; kc += 32) {
        __syncthreads();
        #pragma unroll
        for (int idx = tid; idx < 128 * 32; idx += 256) {
            int r = idx >> 5, k = idx & 31;
            HsT[k * 129 + r] = H[(size_t)(row0 + r) * TT + kc + k];
        }
        #pragma unroll
        for (int idx = tid; idx < 32 * 128; idx += 256) {
            int k = idx >> 7, c = idx & 127;
            Ws[k * 128 + c] = W[(size_t)(kc + k) * DH + c];
        }
        __syncthreads();
        #pragma unroll 4
        for (int k = 0; k < 32; k++) {
            float h[8], w[8];
            #pragma unroll
            for (int i = 0; i < 8; i++) h[i] = HsT[k * 129 + ty * 8 + i];
            float4 w0 = *(const float4*)&Ws[k * 128 + tx * 8];
            float4 w1 = *(const float4*)&Ws[k * 128 + tx * 8 + 4];
            w[0]=w0.x; w[1]=w0.y; w[2]=w0.z; w[3]=w0.w;
            w[4]=w1.x; w[5]=w1.y; w[6]=w1.z; w[7]=w1.w;
            #pragma unroll
            for (int i = 0; i < 8; i++)
                #pragma unroll
                for (int j = 0; j < 8; j++)
                    acc[i][j] += h[i] * w[j];
        }
    }

    float bb[8];
    {
        float4 b0 = *(const float4*)&b[tx * 8];
        float4 b1 = *(const float4*)&b[tx * 8 + 4];
        bb[0]=b0.x; bb[1]=b0.y; bb[2]=b0.z; bb[3]=b0.w;
        bb[4]=b1.x; bb[5]=b1.y; bb[6]=b1.z; bb[7]=b1.w;
    }
    #pragma unroll
    for (int i = 0; i < 8; i++) {
        int r = row0 + ty * 8 + i;
        __nv_bfloat16 t8[8];
        #pragma unroll
        for (int j = 0; j < 8; j++)
            t8[j] = __float2bfloat16((acc[i][j] + bb[j]) * osc);
        *(uint4*)&outp[(size_t)r * DH + tx * 8] = *(const uint4*)t8;
    }
}

// ===========================================================================
// Kernel 2: H -> bf16
// ===========================================================================
__global__ __launch_bounds__(256)
void hconv_kernel(const float* __restrict__ H) {
    size_t i = (size_t)blockIdx.x * 256 + threadIdx.x;
    float4 v = ((const float4*)H)[i];
    __nv_bfloat162 a = __floats2bfloat162_rn(v.x, v.y);
    __nv_bfloat162 b = __floats2bfloat162_rn(v.z, v.w);
    uint2 o;
    o.x = *(uint32_t*)&a;
    o.y = *(uint32_t*)&b;
    ((uint2*)g_Hb)[i] = o;
}

// ===========================================================================
// Kernel 3: flash attention, register-resident P.
// 8 warps: wr = wid>>1 (16 q-rows), wc = wid&1 (64-key k-slice).
// Each warp: S[16,64] -> exp (regs) -> partial O[16,256] over its k-slice.
// Cross-slice O reduction once at the end.
// ===========================================================================
__device__ __forceinline__ void issue_tile(uint32_t sb, int tid, int k0, int stage) {
    {
        const char* src = (const char*)(g_Kb + (size_t)k0 * DH);
        uint32_t dstb = sb + OFF_K + stage * KBYTES;
        #pragma unroll
        for (int i = tid; i < 2048; i += 256) {
            int r = i >> 4, c = i & 15;
            cp16(dstb + r * KS_STRIDE + c * 16, src + r * 256 + c * 16);
        }
    }
    {
        const char* src = (const char*)(g_Hb + (size_t)k0 * TT);
        uint32_t dstb = sb + OFF_H + stage * HBYTES;
        #pragma unroll
        for (int i = tid; i < 4096; i += 256) {
            int r = i >> 5, c = i & 31;
            cp16(dstb + r * HS_STRIDE + c * 16, src + r * 512 + c * 16);
        }
    }
}

__global__ __launch_bounds__(256, 1)
void attn5_kernel(const float* __restrict__ H, float* __restrict__ out) {
    extern __shared__ char sm[];
    const uint32_t sb = smem_u32(sm);
    const int tid = threadIdx.x;
    const int wid = tid >> 5, lane = tid & 31;
    const int wr = wid >> 1, wc = wid & 1;
    const int g = lane >> 2, t = lane & 3;
    const int bl = lane >> 3, rl = lane & 7;
    const int q0 = blockIdx.x * BM;

    // prefetch tile 0
    issue_tile(sb, tid, 0, 0);
    cp_commit();

    // stage Q (64 x 128 bf16) and build persistent A fragments
    for (int i = tid; i < BM * 16; i += 256) {
        int r = i >> 4, c = i & 15;
        uint4 v = *(const uint4*)(g_Qb + (size_t)(q0 + r) * DH + c * 8);
        *(uint4*)(sm + OFF_Q + r * PS_STRIDE + c * 16) = v;
    }
    __syncthreads();

    uint32_t aq[8][4];
    {
        int m = wr * 16 + rl + ((bl & 1) ? 8 : 0);
        #pragma unroll
        for (int s = 0; s < 8; s++) {
            uint32_t addr = sb + OFF_Q + m * PS_STRIDE + s * 32 + ((bl & 2) ? 16 : 0);
            ldsm_x4(aq[s][0], aq[s][1], aq[s][2], aq[s][3], addr);
        }
    }

    float oacc[32][4];
    #pragma unroll
    for (int i = 0; i < 32; i++)
        #pragma unroll
        for (int j = 0; j < 4; j++) oacc[i][j] = 0.f;
    float lsum0 = 0.f, lsum1 = 0.f;
    const int diag_kt = q0 >> 7;

    const int nrow = wc * 64 + rl + ((bl & 2) ? 8 : 0);
    const int kc = (bl & 1) ? 16 : 0;
    const int bk = rl + ((bl & 1) ? 8 : 0);
    const int bn = (bl & 2) ? 8 : 0;

    for (int kt = 0; kt < NT; kt++) {
        const int k0 = kt * BN;
        const int cur = kt & 1;

        cp_wait0();
        __syncthreads();   // tile kt visible; all warps past previous tile's reads

        if (kt + 1 < NT) {
            issue_tile(sb, tid, (kt + 1) * BN, cur ^ 1);
            cp_commit();
        }

        const uint32_t kbase = sb + OFF_K + cur * KBYTES;
        const uint32_t hbase = sb + OFF_H + cur * HBYTES;

        // ---- MMA1: S[16, 64] = Q @ K^T (cols wc*64..+63)
        float sacc[8][4];
        #pragma unroll
        for (int i = 0; i < 8; i++)
            #pragma unroll
            for (int j = 0; j < 4; j++) sacc[i][j] = 0.f;
        #pragma unroll
        for (int s = 0; s < 8; s++) {
            #pragma unroll
            for (int jj = 0; jj < 4; jj++) {
                uint32_t addr = kbase + (nrow + jj * 16) * KS_STRIDE + s * 32 + kc;
                uint32_t b0, b1, b2, b3;
                ldsm_x4(b0, b1, b2, b3, addr);
                mma16816(sacc[2 * jj], aq[s], b0, b1);
                mma16816(sacc[2 * jj + 1], aq[s], b2, b3);
            }
        }

        // ---- exp (logits pre-scaled by log2e -> ex2), diag, row sums, pack P
        uint32_t pa[4][4];
        {
            const int row0 = wr * 16 + g;
            const bool dt = (kt == diag_kt);
            const int grow0 = q0 + row0, grow1 = grow0 + 8;
            #pragma unroll
            for (int jj = 0; jj < 8; jj++) {
                int gcol = k0 + wc * 64 + jj * 8 + 2 * t;
                float p0 = ex2f(sacc[jj][0]);
                float p1 = ex2f(sacc[jj][1]);
                float p2 = ex2f(sacc[jj][2]);
                float p3 = ex2f(sacc[jj][3]);
                if (dt) {   // diagonal logit forced to 0 -> p = 1
                    if (grow0 == gcol)     p0 = 1.f;
                    if (grow0 == gcol + 1) p1 = 1.f;
                    if (grow1 == gcol)     p2 = 1.f;
                    if (grow1 == gcol + 1) p3 = 1.f;
                }
                lsum0 += p0 + p1;
                lsum1 += p2 + p3;
                // C-frag -> A-frag mapping: (c0,c1)->a0/a2, (c2,c3)->a1/a3
                pa[jj >> 1][(jj & 1) ? 2 : 0] = packbf2(p0, p1);
                pa[jj >> 1][(jj & 1) ? 3 : 1] = packbf2(p2, p3);
            }
        }

        // ---- MMA2: O[16, 256] += P[16, 64-slice] @ H[64-slice, 256]
        #pragma unroll
        for (int s2 = 0; s2 < 4; s2++) {
            const int krow = wc * 64 + s2 * 16 + bk;
            #pragma unroll
            for (int jj = 0; jj < 16; jj++) {
                uint32_t addr = hbase + krow * HS_STRIDE + (jj * 16 + bn) * 2;
                uint32_t b0, b1, b2, b3;
                ldsm_x4_t(b0, b1, b2, b3, addr);
                mma16816(oacc[2 * jj], pa[s2], b0, b1);
                mma16816(oacc[2 * jj + 1], pa[s2], b2, b3);
            }
        }
    }

    // ---- epilogue ----
    __syncthreads();   // all tile reads done; smem free for reuse

    // row-sum reduce: quad shuffle then cross-slice via smem
    lsum0 += __shfl_xor_sync(0xffffffffu, lsum0, 1);
    lsum0 += __shfl_xor_sync(0xffffffffu, lsum0, 2);
    lsum1 += __shfl_xor_sync(0xffffffffu, lsum1, 1);
    lsum1 += __shfl_xor_sync(0xffffffffu, lsum1, 2);
    float* Ls = (float*)(sm + OFF_L);
    if (t == 0) {
        Ls[wc * 64 + wr * 16 + g] = lsum0;
        Ls[wc * 64 + wr * 16 + g + 8] = lsum1;
    }

    // O cross-slice reduction: wc=1 publishes partial O, wc=0 combines
    float* osm = (float*)sm;
    if (wc == 1) {
        float* base0 = osm + (wr * 16 + g) * OSM_STRIDE + 2 * t;
        float* base1 = osm + (wr * 16 + g + 8) * OSM_STRIDE + 2 * t;
        #pragma unroll
        for (int jj = 0; jj < 32; jj++) {
            *(float2*)(base0 + jj * 8) = make_float2(oacc[jj][0], oacc[jj][1]);
            *(float2*)(base1 + jj * 8) = make_float2(oacc[jj][2], oacc[jj][3]);
        }
    }
    __syncthreads();

    if (wc == 0) {
        const int r0 = wr * 16 + g;
        const float inv0 = 1.f / (Ls[r0] + Ls[64 + r0]);
        const float inv1 = 1.f / (Ls[r0 + 8] + Ls[64 + r0 + 8]);
        const int grow0 = q0 + r0;
        const float* base0 = osm + r0 * OSM_STRIDE + 2 * t;
        const float* base1 = osm + (r0 + 8) * OSM_STRIDE + 2 * t;
        #pragma unroll
        for (int jj = 0; jj < 32; jj++) {
            int col = jj * 8 + 2 * t;
            float2 x0 = *(const float2*)(base0 + jj * 8);
            float2 x1 = *(const float2*)(base1 + jj * 8);
            float2 h0 = *(const float2*)(H + (size_t)grow0 * TT + col);
            float2 h1 = *(const float2*)(H + (size_t)(grow0 + 8) * TT + col);
            float2 o0, o1;
            o0.x = (oacc[jj][0] + x0.x) * inv0 + h0.x;
            o0.y = (oacc[jj][1] + x0.y) * inv0 + h0.y;
            o1.x = (oacc[jj][2] + x1.x) * inv1 + h1.x;
            o1.y = (oacc[jj][3] + x1.y) * inv1 + h1.y;
            *(float2*)(out + (size_t)grow0 * TT + col) = o0;
            *(float2*)(out + (size_t)(grow0 + 8) * TT + col) = o1;
        }
    }
}

// ===========================================================================
extern "C" void kernel_launch(void* const* d_in, const int* in_sizes, int n_in,
                              void* d_out, int out_size) {
    const float* H  = (const float*)d_in[0];
    const float* Wq = (const float*)d_in[1];
    const float* bq = (const float*)d_in[2];
    const float* Wk = (const float*)d_in[3];
    const float* bk = (const float*)d_in[4];
    float* out = (float*)d_out;

    cudaFuncSetAttribute(attn5_kernel,
                         cudaFuncAttributeMaxDynamicSharedMemorySize, ATTN_SMEM);

    qk_kernel<<<dim3(NN / 128, 2), 256>>>(H, Wq, bq, Wk, bk);
    hconv_kernel<<<(NN * TT / 4) / 256, 256>>>(H);
    attn5_kernel<<<NN / BM, 256, ATTN_SMEM>>>(H, out);
}

// round 7
// speedup vs baseline: 14.2167x; 1.0174x over previous
#include <cuda_runtime.h>
#include <cuda_bf16.h>
#include <cstdint>

#define NN 16384
#define DH 128
#define TT 256
#define QSCALE (0.08838834764831845f * 1.4426950408889634f)  // 1/sqrt(128) * log2(e)

#define BM 64
#define BN 128
#define NT (NN / BN)

// smem layout (bytes) — double-buffered K/H + P (aliased with Q staging) + L
#define KS_STRIDE 272                      // 128 bf16 + 8 pad
#define HS_STRIDE 528                      // 256 bf16 + 8 pad
#define PS_STRIDE 272
#define KBYTES (128 * KS_STRIDE)           // 34816
#define HBYTES (128 * HS_STRIDE)           // 67584
#define OFF_K 0                            // 2 stages
#define OFF_H (2 * KBYTES)                 // 69632, 2 stages
#define OFF_P (OFF_H + 2 * HBYTES)         // 204800: P[64][136 bf16]; Q staging in prologue
#define OFF_L (OFF_P + 64 * PS_STRIDE)     // 222208 (4*64*4 = 1024B)
#define ATTN_SMEM (OFF_L + 4 * 64 * 4)     // 223232

// device-global scratch (allocation-guard safe)
__device__ __nv_bfloat16 g_Qb[NN * DH];          // Q*QSCALE bf16
__device__ __nv_bfloat16 g_Kb[NN * DH];          // K bf16
__device__ __nv_bfloat16 g_Hb[(size_t)NN * TT];  // H bf16

// ===========================================================================
// helpers (sm_80-baseline PTX: portable under compute_103)
// ===========================================================================
__device__ __forceinline__ uint32_t smem_u32(const void* p) {
    uint32_t a;
    asm("{ .reg .u64 t; cvta.to.shared.u64 t, %1; cvt.u32.u64 %0, t; }"
        : "=r"(a) : "l"(p));
    return a;
}
__device__ __forceinline__ void ldsm_x4(uint32_t& r0, uint32_t& r1,
                                        uint32_t& r2, uint32_t& r3, uint32_t a) {
    asm volatile("ldmatrix.sync.aligned.m8n8.x4.shared.b16 {%0,%1,%2,%3}, [%4];"
                 : "=r"(r0), "=r"(r1), "=r"(r2), "=r"(r3) : "r"(a));
}
__device__ __forceinline__ void ldsm_x4_t(uint32_t& r0, uint32_t& r1,
                                          uint32_t& r2, uint32_t& r3, uint32_t a) {
    asm volatile("ldmatrix.sync.aligned.m8n8.x4.trans.shared.b16 {%0,%1,%2,%3}, [%4];"
                 : "=r"(r0), "=r"(r1), "=r"(r2), "=r"(r3) : "r"(a));
}
__device__ __forceinline__ void mma16816(float* d, const uint32_t* a,
                                         uint32_t b0, uint32_t b1) {
    asm volatile("mma.sync.aligned.m16n8k16.row.col.f32.bf16.bf16.f32 "
                 "{%0,%1,%2,%3},{%4,%5,%6,%7},{%8,%9},{%0,%1,%2,%3};"
                 : "+f"(d[0]), "+f"(d[1]), "+f"(d[2]), "+f"(d[3])
                 : "r"(a[0]), "r"(a[1]), "r"(a[2]), "r"(a[3]), "r"(b0), "r"(b1));
}
__device__ __forceinline__ void cp16(uint32_t dst, const void* src) {
    asm volatile("cp.async.cg.shared.global [%0], [%1], 16;"
                 :: "r"(dst), "l"(src) : "memory");
}
__device__ __forceinline__ void cp_commit() {
    asm volatile("cp.async.commit_group;" ::: "memory");
}
__device__ __forceinline__ void cp_wait0() {
    asm volatile("cp.async.wait_group 0;" ::: "memory");
}
__device__ __forceinline__ float ex2f(float x) {
    float y;
    asm("ex2.approx.f32 %0, %1;" : "=f"(y) : "f"(x));
    return y;
}
__device__ __forceinline__ uint32_t packbf2(float lo, float hi) {
    __nv_bfloat162 v = __floats2bfloat162_rn(lo, hi);
    return *(uint32_t*)&v;
}

// ===========================================================================
// Kernel 1: Q = (H Wq + bq)*QSCALE -> bf16 ; K = H Wk + bk -> bf16
// ===========================================================================
__global__ __launch_bounds__(256)
void qk_kernel(const float* __restrict__ H,
               const float* __restrict__ Wq, const float* __restrict__ bq,
               const float* __restrict__ Wk, const float* __restrict__ bk) {
    __shared__ float HsT[32 * 129];
    __shared__ float Ws[32 * 128];

    const float* W = blockIdx.y ? Wk : Wq;
    const float* b = blockIdx.y ? bk : bq;
    __nv_bfloat16* outp = blockIdx.y ? g_Kb : g_Qb;
    const float osc = blockIdx.y ? 1.0f : QSCALE;

    const int tid = threadIdx.x;
    const int ty = tid >> 4, tx = tid & 15;
    const int row0 = blockIdx.x * 128;

    float acc[8][8];
    #pragma unroll
    for (int i = 0; i < 8; i++)
        #pragma unroll
        for (int j = 0; j < 8; j++) acc[i][j] = 0.f;

    for (int kc = 0; kc < TT; kc += 32) {
        __syncthreads();
        #pragma unroll
        for (int idx = tid; idx < 128 * 32; idx += 256) {
            int r = idx >> 5, k = idx & 31;
            HsT[k * 129 + r] = H[(size_t)(row0 + r) * TT + kc + k];
        }
        #pragma unroll
        for (int idx = tid; idx < 32 * 128; idx += 256) {
            int k = idx >> 7, c = idx & 127;
            Ws[k * 128 + c] = W[(size_t)(kc + k) * DH + c];
        }
        __syncthreads();
        #pragma unroll 4
        for (int k = 0; k < 32; k++) {
            float h[8], w[8];
            #pragma unroll
            for (int i = 0; i < 8; i++) h[i] = HsT[k * 129 + ty * 8 + i];
            float4 w0 = *(const float4*)&Ws[k * 128 + tx * 8];
            float4 w1 = *(const float4*)&Ws[k * 128 + tx * 8 + 4];
            w[0]=w0.x; w[1]=w0.y; w[2]=w0.z; w[3]=w0.w;
            w[4]=w1.x; w[5]=w1.y; w[6]=w1.z; w[7]=w1.w;
            #pragma unroll
            for (int i = 0; i < 8; i++)
                #pragma unroll
                for (int j = 0; j < 8; j++)
                    acc[i][j] += h[i] * w[j];
        }
    }

    float bb[8];
    {
        float4 b0 = *(const float4*)&b[tx * 8];
        float4 b1 = *(const float4*)&b[tx * 8 + 4];
        bb[0]=b0.x; bb[1]=b0.y; bb[2]=b0.z; bb[3]=b0.w;
        bb[4]=b1.x; bb[5]=b1.y; bb[6]=b1.z; bb[7]=b1.w;
    }
    #pragma unroll
    for (int i = 0; i < 8; i++) {
        int r = row0 + ty * 8 + i;
        __nv_bfloat16 t8[8];
        #pragma unroll
        for (int j = 0; j < 8; j++)
            t8[j] = __float2bfloat16((acc[i][j] + bb[j]) * osc);
        *(uint4*)&outp[(size_t)r * DH + tx * 8] = *(const uint4*)t8;
    }
}

// ===========================================================================
// Kernel 2: H -> bf16
// ===========================================================================
__global__ __launch_bounds__(256)
void hconv_kernel(const float* __restrict__ H) {
    size_t i = (size_t)blockIdx.x * 256 + threadIdx.x;
    float4 v = ((const float4*)H)[i];
    __nv_bfloat162 a = __floats2bfloat162_rn(v.x, v.y);
    __nv_bfloat162 b = __floats2bfloat162_rn(v.z, v.w);
    uint2 o;
    o.x = *(uint32_t*)&a;
    o.y = *(uint32_t*)&b;
    ((uint2*)g_Hb)[i] = o;
}

// ===========================================================================
// Kernel 3: flash attention. 8 warps: wr = wid>>2 (32 q-rows),
// wq = wid&3 (MMA1: 32-key slice; MMA2: 64-col slice, FULL 128 keys).
// P goes through smem so every key reaches every output column.
// No O cross-warp reduction needed.
// ===========================================================================
__device__ __forceinline__ void issue_tile(uint32_t sb, int tid, int k0, int stage) {
    {
        const char* src = (const char*)(g_Kb + (size_t)k0 * DH);
        uint32_t dstb = sb + OFF_K + stage * KBYTES;
        #pragma unroll
        for (int i = tid; i < 2048; i += 256) {
            int r = i >> 4, c = i & 15;
            cp16(dstb + r * KS_STRIDE + c * 16, src + r * 256 + c * 16);
        }
    }
    {
        const char* src = (const char*)(g_Hb + (size_t)k0 * TT);
        uint32_t dstb = sb + OFF_H + stage * HBYTES;
        #pragma unroll
        for (int i = tid; i < 4096; i += 256) {
            int r = i >> 5, c = i & 31;
            cp16(dstb + r * HS_STRIDE + c * 16, src + r * 512 + c * 16);
        }
    }
}

__global__ __launch_bounds__(256, 1)
void attn7_kernel(const float* __restrict__ H, float* __restrict__ out) {
    extern __shared__ char sm[];
    const uint32_t sb = smem_u32(sm);
    const int tid = threadIdx.x;
    const int wid = tid >> 5, lane = tid & 31;
    const int wr = wid >> 2, wq = wid & 3;
    const int g = lane >> 2, t = lane & 3;
    const int bl = lane >> 3, rl = lane & 7;
    const int q0 = blockIdx.x * BM;

    // prefetch tile 0
    issue_tile(sb, tid, 0, 0);
    cp_commit();

    // stage Q (64 x 128 bf16) into the P region (prologue-only aliasing)
    for (int i = tid; i < BM * 16; i += 256) {
        int r = i >> 4, c = i & 15;
        uint4 v = *(const uint4*)(g_Qb + (size_t)(q0 + r) * DH + c * 8);
        *(uint4*)(sm + OFF_P + r * PS_STRIDE + c * 16) = v;
    }
    __syncthreads();

    // persistent Q A-frags: 2 m-blocks (rows wr*32 .. +31)
    uint32_t aq[2][8][4];
    #pragma unroll
    for (int mb = 0; mb < 2; mb++) {
        int m = wr * 32 + mb * 16 + rl + ((bl & 1) ? 8 : 0);
        #pragma unroll
        for (int s = 0; s < 8; s++) {
            uint32_t addr = sb + OFF_P + m * PS_STRIDE + s * 32 + ((bl & 2) ? 16 : 0);
            ldsm_x4(aq[mb][s][0], aq[mb][s][1], aq[mb][s][2], aq[mb][s][3], addr);
        }
    }
    __syncthreads();   // everyone done reading Q before P overwrites the region

    float oacc[16][4];              // O[32 rows x 64 cols]: [mb*8 + jj*2 + n8][4]
    #pragma unroll
    for (int i = 0; i < 16; i++)
        #pragma unroll
        for (int j = 0; j < 4; j++) oacc[i][j] = 0.f;
    float lsum[4] = {0.f, 0.f, 0.f, 0.f};    // rows g, g+8 (mb0), g+16, g+24 (mb1)
    const int diag_kt = q0 >> 7;

    const int nrow = wq * 32 + rl + ((bl & 2) ? 8 : 0);   // MMA1 B key row
    const int kc = (bl & 1) ? 16 : 0;
    const int am = rl + ((bl & 1) ? 8 : 0);               // MMA2 A row comp
    const int akc = (bl & 2) ? 16 : 0;
    const int bk = rl + ((bl & 1) ? 8 : 0);               // MMA2 B key row comp
    const int bn = (bl & 2) ? 8 : 0;

    for (int kt = 0; kt < NT; kt++) {
        const int k0 = kt * BN;
        const int cur = kt & 1;

        cp_wait0();
        __syncthreads();   // tile kt ready; P free (MMA2(kt-1) reads done)

        if (kt + 1 < NT) {
            issue_tile(sb, tid, (kt + 1) * BN, cur ^ 1);
            cp_commit();
        }

        const uint32_t kbase = sb + OFF_K + cur * KBYTES;
        const uint32_t hbase = sb + OFF_H + cur * HBYTES;

        // ---- MMA1: S[32, 32-key slice] = Q @ K^T
        float sacc[2][4][4];
        #pragma unroll
        for (int mb = 0; mb < 2; mb++)
            #pragma unroll
            for (int jj = 0; jj < 4; jj++)
                #pragma unroll
                for (int x = 0; x < 4; x++) sacc[mb][jj][x] = 0.f;

        #pragma unroll
        for (int s = 0; s < 8; s++) {
            #pragma unroll
            for (int nb = 0; nb < 2; nb++) {
                uint32_t addr = kbase + (nrow + nb * 16) * KS_STRIDE + s * 32 + kc;
                uint32_t b0, b1, b2, b3;
                ldsm_x4(b0, b1, b2, b3, addr);
                #pragma unroll
                for (int mb = 0; mb < 2; mb++) {
                    mma16816(sacc[mb][2 * nb], aq[mb][s], b0, b1);
                    mma16816(sacc[mb][2 * nb + 1], aq[mb][s], b2, b3);
                }
            }
        }

        // ---- exp (ex2; scale folded), diag->1, row sums, publish P to smem
        {
            const bool dt = (kt == diag_kt);
            #pragma unroll
            for (int mb = 0; mb < 2; mb++) {
                const int row0 = wr * 32 + mb * 16 + g;
                const int grow0 = q0 + row0, grow1 = grow0 + 8;
                #pragma unroll
                for (int jj = 0; jj < 4; jj++) {
                    int col = wq * 32 + jj * 8 + 2 * t;
                    int gcol = k0 + col;
                    float p0 = ex2f(sacc[mb][jj][0]);
                    float p1 = ex2f(sacc[mb][jj][1]);
                    float p2 = ex2f(sacc[mb][jj][2]);
                    float p3 = ex2f(sacc[mb][jj][3]);
                    if (dt) {   // diagonal logit forced to 0 -> p = 1
                        if (grow0 == gcol)     p0 = 1.f;
                        if (grow0 == gcol + 1) p1 = 1.f;
                        if (grow1 == gcol)     p2 = 1.f;
                        if (grow1 == gcol + 1) p3 = 1.f;
                    }
                    lsum[2 * mb]     += p0 + p1;
                    lsum[2 * mb + 1] += p2 + p3;
                    *(uint32_t*)(sm + OFF_P + row0 * PS_STRIDE + col * 2) =
                        packbf2(p0, p1);
                    *(uint32_t*)(sm + OFF_P + (row0 + 8) * PS_STRIDE + col * 2) =
                        packbf2(p2, p3);
                }
            }
        }
        __syncthreads();   // P visible to all warps

        // ---- MMA2: O[32, 64-col slice] += P[32, 128] @ H[128, 64-col slice]
        #pragma unroll
        for (int s2 = 0; s2 < 8; s2++) {
            uint32_t pa[2][4];
            #pragma unroll
            for (int mb = 0; mb < 2; mb++) {
                uint32_t addr = sb + OFF_P + (wr * 32 + mb * 16 + am) * PS_STRIDE
                              + s2 * 32 + akc;
                ldsm_x4(pa[mb][0], pa[mb][1], pa[mb][2], pa[mb][3], addr);
            }
            const int krow = s2 * 16 + bk;
            #pragma unroll
            for (int jj = 0; jj < 4; jj++) {
                uint32_t addr = hbase + krow * HS_STRIDE + (wq * 64 + jj * 16 + bn) * 2;
                uint32_t b0, b1, b2, b3;
                ldsm_x4_t(b0, b1, b2, b3, addr);
                #pragma unroll
                for (int mb = 0; mb < 2; mb++) {
                    mma16816(oacc[mb * 8 + jj * 2],     pa[mb], b0, b1);
                    mma16816(oacc[mb * 8 + jj * 2 + 1], pa[mb], b2, b3);
                }
            }
        }
    }

    // ---- epilogue ----
    // row sums: quad reduce, publish per-key-slice partials
    #pragma unroll
    for (int i = 0; i < 4; i++) {
        lsum[i] += __shfl_xor_sync(0xffffffffu, lsum[i], 1);
        lsum[i] += __shfl_xor_sync(0xffffffffu, lsum[i], 2);
    }
    float* Ls = (float*)(sm + OFF_L);
    if (t == 0) {
        int r = wr * 32 + g;
        Ls[wq * 64 + r]      = lsum[0];
        Ls[wq * 64 + r + 8]  = lsum[1];
        Ls[wq * 64 + r + 16] = lsum[2];
        Ls[wq * 64 + r + 24] = lsum[3];
    }
    __syncthreads();

    // out = O/l + H — each warp owns rows wr*32..+31, cols wq*64..+63
    #pragma unroll
    for (int mb = 0; mb < 2; mb++) {
        int row0 = wr * 32 + mb * 16 + g;
        float invA = 1.f / (Ls[row0] + Ls[64 + row0] + Ls[128 + row0] + Ls[192 + row0]);
        float invB = 1.f / (Ls[row0 + 8] + Ls[64 + row0 + 8] +
                            Ls[128 + row0 + 8] + Ls[192 + row0 + 8]);
        int grow0 = q0 + row0;
        #pragma unroll
        for (int jj = 0; jj < 4; jj++) {
            #pragma unroll
            for (int n8 = 0; n8 < 2; n8++) {
                int col = wq * 64 + jj * 16 + n8 * 8 + 2 * t;
                const float* oa = oacc[mb * 8 + jj * 2 + n8];
                float2 h0 = *(const float2*)(H + (size_t)grow0 * TT + col);
                float2 h1 = *(const float2*)(H + (size_t)(grow0 + 8) * TT + col);
                float2 o0, o1;
                o0.x = oa[0] * invA + h0.x;
                o0.y = oa[1] * invA + h0.y;
                o1.x = oa[2] * invB + h1.x;
                o1.y = oa[3] * invB + h1.y;
                *(float2*)(out + (size_t)grow0 * TT + col) = o0;
                *(float2*)(out + (size_t)(grow0 + 8) * TT + col) = o1;
            }
        }
    }
}

// ===========================================================================
extern "C" void kernel_launch(void* const* d_in, const int* in_sizes, int n_in,
                              void* d_out, int out_size) {
    const float* H  = (const float*)d_in[0];
    const float* Wq = (const float*)d_in[1];
    const float* bq = (const float*)d_in[2];
    const float* Wk = (const float*)d_in[3];
    const float* bk = (const float*)d_in[4];
    float* out = (float*)d_out;

    cudaFuncSetAttribute(attn7_kernel,
                         cudaFuncAttributeMaxDynamicSharedMemorySize, ATTN_SMEM);

    qk_kernel<<<dim3(NN / 128, 2), 256>>>(H, Wq, bq, Wk, bk);
    hconv_kernel<<<(NN * TT / 4) / 256, 256>>>(H);
    attn7_kernel<<<NN / BM, 256, ATTN_SMEM>>>(H, out);
}

// round 8
// speedup vs baseline: 14.4239x; 1.0146x over previous
#include <cuda_runtime.h>
#include <cuda_bf16.h>
#include <cstdint>

#define NN 16384
#define DH 128
#define TT 256
#define QSCALE (0.08838834764831845f * 1.4426950408889634f)  // 1/sqrt(128) * log2(e)

#define BM 64
#define BN 128
#define NT (NN / BN)

// smem layout (bytes) — double-buffered K/H + P (aliased with Q staging) + L
#define KS_STRIDE 272                      // 128 bf16 + 8 pad
#define HS_STRIDE 528                      // 256 bf16 + 8 pad
#define PS_STRIDE 272
#define KBYTES (128 * KS_STRIDE)           // 34816
#define HBYTES (128 * HS_STRIDE)           // 67584
#define OFF_K 0                            // 2 stages
#define OFF_H (2 * KBYTES)                 // 69632, 2 stages
#define OFF_P (OFF_H + 2 * HBYTES)         // 204800: P[64][136 bf16]; Q staging in prologue
#define OFF_L (OFF_P + 64 * PS_STRIDE)     // 222208 (4*64*4 = 1024B)
#define ATTN_SMEM (OFF_L + 4 * 64 * 4)     // 223232

// device-global scratch (allocation-guard safe)
__device__ __nv_bfloat16 g_Qb[NN * DH];          // Q*QSCALE bf16
__device__ __nv_bfloat16 g_Kb[NN * DH];          // K bf16
__device__ __nv_bfloat16 g_Hb[(size_t)NN * TT];  // H bf16

// ===========================================================================
// helpers (sm_80-baseline PTX: portable under compute_103)
// ===========================================================================
__device__ __forceinline__ uint32_t smem_u32(const void* p) {
    uint32_t a;
    asm("{ .reg .u64 t; cvta.to.shared.u64 t, %1; cvt.u32.u64 %0, t; }"
        : "=r"(a) : "l"(p));
    return a;
}
__device__ __forceinline__ void ldsm_x4(uint32_t& r0, uint32_t& r1,
                                        uint32_t& r2, uint32_t& r3, uint32_t a) {
    asm volatile("ldmatrix.sync.aligned.m8n8.x4.shared.b16 {%0,%1,%2,%3}, [%4];"
                 : "=r"(r0), "=r"(r1), "=r"(r2), "=r"(r3) : "r"(a));
}
__device__ __forceinline__ void ldsm_x4_t(uint32_t& r0, uint32_t& r1,
                                          uint32_t& r2, uint32_t& r3, uint32_t a) {
    asm volatile("ldmatrix.sync.aligned.m8n8.x4.trans.shared.b16 {%0,%1,%2,%3}, [%4];"
                 : "=r"(r0), "=r"(r1), "=r"(r2), "=r"(r3) : "r"(a));
}
__device__ __forceinline__ void mma16816(float* d, const uint32_t* a,
                                         uint32_t b0, uint32_t b1) {
    asm volatile("mma.sync.aligned.m16n8k16.row.col.f32.bf16.bf16.f32 "
                 "{%0,%1,%2,%3},{%4,%5,%6,%7},{%8,%9},{%0,%1,%2,%3};"
                 : "+f"(d[0]), "+f"(d[1]), "+f"(d[2]), "+f"(d[3])
                 : "r"(a[0]), "r"(a[1]), "r"(a[2]), "r"(a[3]), "r"(b0), "r"(b1));
}
__device__ __forceinline__ void cp16(uint32_t dst, const void* src) {
    asm volatile("cp.async.cg.shared.global [%0], [%1], 16;"
                 :: "r"(dst), "l"(src) : "memory");
}
__device__ __forceinline__ void cp_commit() {
    asm volatile("cp.async.commit_group;" ::: "memory");
}
__device__ __forceinline__ void cp_wait0() {
    asm volatile("cp.async.wait_group 0;" ::: "memory");
}
__device__ __forceinline__ float ex2f(float x) {
    float y;
    asm("ex2.approx.f32 %0, %1;" : "=f"(y) : "f"(x));
    return y;
}
__device__ __forceinline__ uint32_t packbf2(float lo, float hi) {
    __nv_bfloat162 v = __floats2bfloat162_rn(lo, hi);
    return *(uint32_t*)&v;
}
// group-local named barrier: 128 threads of one row-group
__device__ __forceinline__ void bar_grp(int id) {
    asm volatile("bar.sync %0, %1;" :: "r"(id), "r"(128) : "memory");
}

// ===========================================================================
// Kernel 1: Q = (H Wq + bq)*QSCALE -> bf16 ; K = H Wk + bk -> bf16
// 2 CTAs/SM (forced <=128 regs) to hide FMA/LDS latency.
// ===========================================================================
__global__ void __launch_bounds__(256, 2)
qk_kernel(const float* __restrict__ H,
          const float* __restrict__ Wq, const float* __restrict__ bq,
          const float* __restrict__ Wk, const float* __restrict__ bk) {
    __shared__ float HsT[32 * 129];
    __shared__ float Ws[32 * 128];

    const float* W = blockIdx.y ? Wk : Wq;
    const float* b = blockIdx.y ? bk : bq;
    __nv_bfloat16* outp = blockIdx.y ? g_Kb : g_Qb;
    const float osc = blockIdx.y ? 1.0f : QSCALE;

    const int tid = threadIdx.x;
    const int ty = tid >> 4, tx = tid & 15;
    const int row0 = blockIdx.x * 128;

    float acc[8][8];
    #pragma unroll
    for (int i = 0; i < 8; i++)
        #pragma unroll
        for (int j = 0; j < 8; j++) acc[i][j] = 0.f;

    for (int kc = 0; kc < TT; kc += 32) {
        __syncthreads();
        #pragma unroll
        for (int idx = tid; idx < 128 * 32; idx += 256) {
            int r = idx >> 5, k = idx & 31;
            HsT[k * 129 + r] = H[(size_t)(row0 + r) * TT + kc + k];
        }
        #pragma unroll
        for (int idx = tid; idx < 32 * 128; idx += 256) {
            int k = idx >> 7, c = idx & 127;
            Ws[k * 128 + c] = W[(size_t)(kc + k) * DH + c];
        }
        __syncthreads();
        #pragma unroll 4
        for (int k = 0; k < 32; k++) {
            float h[8], w[8];
            #pragma unroll
            for (int i = 0; i < 8; i++) h[i] = HsT[k * 129 + ty * 8 + i];
            float4 w0 = *(const float4*)&Ws[k * 128 + tx * 8];
            float4 w1 = *(const float4*)&Ws[k * 128 + tx * 8 + 4];
            w[0]=w0.x; w[1]=w0.y; w[2]=w0.z; w[3]=w0.w;
            w[4]=w1.x; w[5]=w1.y; w[6]=w1.z; w[7]=w1.w;
            #pragma unroll
            for (int i = 0; i < 8; i++)
                #pragma unroll
                for (int j = 0; j < 8; j++)
                    acc[i][j] += h[i] * w[j];
        }
    }

    float bb[8];
    {
        float4 b0 = *(const float4*)&b[tx * 8];
        float4 b1 = *(const float4*)&b[tx * 8 + 4];
        bb[0]=b0.x; bb[1]=b0.y; bb[2]=b0.z; bb[3]=b0.w;
        bb[4]=b1.x; bb[5]=b1.y; bb[6]=b1.z; bb[7]=b1.w;
    }
    #pragma unroll
    for (int i = 0; i < 8; i++) {
        int r = row0 + ty * 8 + i;
        __nv_bfloat16 t8[8];
        #pragma unroll
        for (int j = 0; j < 8; j++)
            t8[j] = __float2bfloat16((acc[i][j] + bb[j]) * osc);
        *(uint4*)&outp[(size_t)r * DH + tx * 8] = *(const uint4*)t8;
    }
}

// ===========================================================================
// Kernel 2: H -> bf16
// ===========================================================================
__global__ __launch_bounds__(256)
void hconv_kernel(const float* __restrict__ H) {
    size_t i = (size_t)blockIdx.x * 256 + threadIdx.x;
    float4 v = ((const float4*)H)[i];
    __nv_bfloat162 a = __floats2bfloat162_rn(v.x, v.y);
    __nv_bfloat162 b = __floats2bfloat162_rn(v.z, v.w);
    uint2 o;
    o.x = *(uint32_t*)&a;
    o.y = *(uint32_t*)&b;
    ((uint2*)g_Hb)[i] = o;
}

// ===========================================================================
// Kernel 3: flash attention. 8 warps: wr = wid>>2 (row group, 32 q-rows),
// wq = wid&3 (MMA1: 32-key slice; MMA2: 64-col slice, FULL 128 keys).
// P is row-partitioned by group -> P-publish barrier is GROUP-LOCAL,
// letting the two row-groups' exp (MUFU) and MMA2 (tensor) phases overlap.
// ===========================================================================
__device__ __forceinline__ void issue_tile(uint32_t sb, int tid, int k0, int stage) {
    {
        const char* src = (const char*)(g_Kb + (size_t)k0 * DH);
        uint32_t dstb = sb + OFF_K + stage * KBYTES;
        #pragma unroll
        for (int i = tid; i < 2048; i += 256) {
            int r = i >> 4, c = i & 15;
            cp16(dstb + r * KS_STRIDE + c * 16, src + r * 256 + c * 16);
        }
    }
    {
        const char* src = (const char*)(g_Hb + (size_t)k0 * TT);
        uint32_t dstb = sb + OFF_H + stage * HBYTES;
        #pragma unroll
        for (int i = tid; i < 4096; i += 256) {
            int r = i >> 5, c = i & 31;
            cp16(dstb + r * HS_STRIDE + c * 16, src + r * 512 + c * 16);
        }
    }
}

__global__ __launch_bounds__(256, 1)
void attn8_kernel(const float* __restrict__ H, float* __restrict__ out) {
    extern __shared__ char sm[];
    const uint32_t sb = smem_u32(sm);
    const int tid = threadIdx.x;
    const int wid = tid >> 5, lane = tid & 31;
    const int wr = wid >> 2, wq = wid & 3;
    const int g = lane >> 2, t = lane & 3;
    const int bl = lane >> 3, rl = lane & 7;
    const int q0 = blockIdx.x * BM;

    // prefetch tile 0
    issue_tile(sb, tid, 0, 0);
    cp_commit();

    // stage Q (64 x 128 bf16) into the P region (prologue-only aliasing)
    for (int i = tid; i < BM * 16; i += 256) {
        int r = i >> 4, c = i & 15;
        uint4 v = *(const uint4*)(g_Qb + (size_t)(q0 + r) * DH + c * 8);
        *(uint4*)(sm + OFF_P + r * PS_STRIDE + c * 16) = v;
    }
    __syncthreads();

    // persistent Q A-frags: 2 m-blocks (rows wr*32 .. +31)
    uint32_t aq[2][8][4];
    #pragma unroll
    for (int mb = 0; mb < 2; mb++) {
        int m = wr * 32 + mb * 16 + rl + ((bl & 1) ? 8 : 0);
        #pragma unroll
        for (int s = 0; s < 8; s++) {
            uint32_t addr = sb + OFF_P + m * PS_STRIDE + s * 32 + ((bl & 2) ? 16 : 0);
            ldsm_x4(aq[mb][s][0], aq[mb][s][1], aq[mb][s][2], aq[mb][s][3], addr);
        }
    }
    __syncthreads();   // everyone done reading Q before P overwrites the region

    float oacc[16][4];              // O[32 rows x 64 cols]: [mb*8 + jj*2 + n8][4]
    #pragma unroll
    for (int i = 0; i < 16; i++)
        #pragma unroll
        for (int j = 0; j < 4; j++) oacc[i][j] = 0.f;
    float lsum[4] = {0.f, 0.f, 0.f, 0.f};    // rows g, g+8 (mb0), g+16, g+24 (mb1)
    const int diag_kt = q0 >> 7;

    const int nrow = wq * 32 + rl + ((bl & 2) ? 8 : 0);   // MMA1 B key row
    const int kc = (bl & 1) ? 16 : 0;
    const int am = rl + ((bl & 1) ? 8 : 0);               // MMA2 A row comp
    const int akc = (bl & 2) ? 16 : 0;
    const int bk = rl + ((bl & 1) ? 8 : 0);               // MMA2 B key row comp
    const int bn = (bl & 2) ? 8 : 0;

    for (int kt = 0; kt < NT; kt++) {
        const int k0 = kt * BN;
        const int cur = kt & 1;

        cp_wait0();
        __syncthreads();   // tile kt ready; prev tile reads done in BOTH groups

        if (kt + 1 < NT) {
            issue_tile(sb, tid, (kt + 1) * BN, cur ^ 1);
            cp_commit();
        }

        const uint32_t kbase = sb + OFF_K + cur * KBYTES;
        const uint32_t hbase = sb + OFF_H + cur * HBYTES;

        // ---- MMA1: S[32, 32-key slice] = Q @ K^T
        float sacc[2][4][4];
        #pragma unroll
        for (int mb = 0; mb < 2; mb++)
            #pragma unroll
            for (int jj = 0; jj < 4; jj++)
                #pragma unroll
                for (int x = 0; x < 4; x++) sacc[mb][jj][x] = 0.f;

        #pragma unroll
        for (int s = 0; s < 8; s++) {
            #pragma unroll
            for (int nb = 0; nb < 2; nb++) {
                uint32_t addr = kbase + (nrow + nb * 16) * KS_STRIDE + s * 32 + kc;
                uint32_t b0, b1, b2, b3;
                ldsm_x4(b0, b1, b2, b3, addr);
                #pragma unroll
                for (int mb = 0; mb < 2; mb++) {
                    mma16816(sacc[mb][2 * nb], aq[mb][s], b0, b1);
                    mma16816(sacc[mb][2 * nb + 1], aq[mb][s], b2, b3);
                }
            }
        }

        // ---- exp (ex2; scale folded), diag->1, row sums, publish P to smem
        {
            const bool dt = (kt == diag_kt);
            #pragma unroll
            for (int mb = 0; mb < 2; mb++) {
                const int row0 = wr * 32 + mb * 16 + g;
                const int grow0 = q0 + row0, grow1 = grow0 + 8;
                #pragma unroll
                for (int jj = 0; jj < 4; jj++) {
                    int col = wq * 32 + jj * 8 + 2 * t;
                    int gcol = k0 + col;
                    float p0 = ex2f(sacc[mb][jj][0]);
                    float p1 = ex2f(sacc[mb][jj][1]);
                    float p2 = ex2f(sacc[mb][jj][2]);
                    float p3 = ex2f(sacc[mb][jj][3]);
                    if (dt) {   // diagonal logit forced to 0 -> p = 1
                        if (grow0 == gcol)     p0 = 1.f;
                        if (grow0 == gcol + 1) p1 = 1.f;
                        if (grow1 == gcol)     p2 = 1.f;
                        if (grow1 == gcol + 1) p3 = 1.f;
                    }
                    lsum[2 * mb]     += p0 + p1;
                    lsum[2 * mb + 1] += p2 + p3;
                    *(uint32_t*)(sm + OFF_P + row0 * PS_STRIDE + col * 2) =
                        packbf2(p0, p1);
                    *(uint32_t*)(sm + OFF_P + (row0 + 8) * PS_STRIDE + col * 2) =
                        packbf2(p2, p3);
                }
            }
        }
        bar_grp(1 + wr);   // P rows of THIS group visible to its 4 warps only

        // ---- MMA2: O[32, 64-col slice] += P[32, 128] @ H[128, 64-col slice]
        #pragma unroll
        for (int s2 = 0; s2 < 8; s2++) {
            uint32_t pa[2][4];
            #pragma unroll
            for (int mb = 0; mb < 2; mb++) {
                uint32_t addr = sb + OFF_P + (wr * 32 + mb * 16 + am) * PS_STRIDE
                              + s2 * 32 + akc;
                ldsm_x4(pa[mb][0], pa[mb][1], pa[mb][2], pa[mb][3], addr);
            }
            const int krow = s2 * 16 + bk;
            #pragma unroll
            for (int jj = 0; jj < 4; jj++) {
                uint32_t addr = hbase + krow * HS_STRIDE + (wq * 64 + jj * 16 + bn) * 2;
                uint32_t b0, b1, b2, b3;
                ldsm_x4_t(b0, b1, b2, b3, addr);
                #pragma unroll
                for (int mb = 0; mb < 2; mb++) {
                    mma16816(oacc[mb * 8 + jj * 2],     pa[mb], b0, b1);
                    mma16816(oacc[mb * 8 + jj * 2 + 1], pa[mb], b2, b3);
                }
            }
        }
    }

    // ---- epilogue ----
    // row sums: quad reduce, publish per-key-slice partials
    #pragma unroll
    for (int i = 0; i < 4; i++) {
        lsum[i] += __shfl_xor_sync(0xffffffffu, lsum[i], 1);
        lsum[i] += __shfl_xor_sync(0xffffffffu, lsum[i], 2);
    }
    float* Ls = (float*)(sm + OFF_L);
    if (t == 0) {
        int r = wr * 32 + g;
        Ls[wq * 64 + r]      = lsum[0];
        Ls[wq * 64 + r + 8]  = lsum[1];
        Ls[wq * 64 + r + 16] = lsum[2];
        Ls[wq * 64 + r + 24] = lsum[3];
    }
    __syncthreads();

    // out = O/l + H — each warp owns rows wr*32..+31, cols wq*64..+63
    #pragma unroll
    for (int mb = 0; mb < 2; mb++) {
        int row0 = wr * 32 + mb * 16 + g;
        float invA = 1.f / (Ls[row0] + Ls[64 + row0] + Ls[128 + row0] + Ls[192 + row0]);
        float invB = 1.f / (Ls[row0 + 8] + Ls[64 + row0 + 8] +
                            Ls[128 + row0 + 8] + Ls[192 + row0 + 8]);
        int grow0 = q0 + row0;
        #pragma unroll
        for (int jj = 0; jj < 4; jj++) {
            #pragma unroll
            for (int n8 = 0; n8 < 2; n8++) {
                int col = wq * 64 + jj * 16 + n8 * 8 + 2 * t;
                const float* oa = oacc[mb * 8 + jj * 2 + n8];
                float2 h0 = *(const float2*)(H + (size_t)grow0 * TT + col);
                float2 h1 = *(const float2*)(H + (size_t)(grow0 + 8) * TT + col);
                float2 o0, o1;
                o0.x = oa[0] * invA + h0.x;
                o0.y = oa[1] * invA + h0.y;
                o1.x = oa[2] * invB + h1.x;
                o1.y = oa[3] * invB + h1.y;
                *(float2*)(out + (size_t)grow0 * TT + col) = o0;
                *(float2*)(out + (size_t)(grow0 + 8) * TT + col) = o1;
            }
        }
    }
}

// ===========================================================================
extern "C" void kernel_launch(void* const* d_in, const int* in_sizes, int n_in,
                              void* d_out, int out_size) {
    const float* H  = (const float*)d_in[0];
    const float* Wq = (const float*)d_in[1];
    const float* bq = (const float*)d_in[2];
    const float* Wk = (const float*)d_in[3];
    const float* bk = (const float*)d_in[4];
    float* out = (float*)d_out;

    cudaFuncSetAttribute(attn8_kernel,
                         cudaFuncAttributeMaxDynamicSharedMemorySize, ATTN_SMEM);

    qk_kernel<<<dim3(NN / 128, 2), 256>>>(H, Wq, bq, Wk, bk);
    hconv_kernel<<<(NN * TT / 4) / 256, 256>>>(H);
    attn8_kernel<<<NN / BM, 256, ATTN_SMEM>>>(H, out);
}